// round 2
// baseline (speedup 1.0000x reference)
#include <cuda_runtime.h>
#include <math.h>

#define Nn 8192
#define Dd 64

// ---------------- device scratch (static allocs are allowed) ----------------
__device__ float    g_zmp[Nn * Dd];                 // normalized z_mp
__device__ float    g_zsc[Nn * Dd];                 // normalized z_sc
__device__ unsigned g_bits[(size_t)Nn * Nn / 32];   // pos bitmask, 8 MB
__device__ float    g_acc[8][Nn];                   // A1,B1,A2,B2,A3,B3,A4,B4

// ---------------- packed f32x2 helpers (Blackwell) ----------------
typedef unsigned long long u64;
__device__ __forceinline__ u64 pk2s(float x) {
    u64 r; asm("mov.b64 %0,{%1,%1};" : "=l"(r) : "f"(x)); return r;
}
__device__ __forceinline__ u64 pk2(float x, float y) {
    u64 r; asm("mov.b64 %0,{%1,%2};" : "=l"(r) : "f"(x), "f"(y)); return r;
}
__device__ __forceinline__ void fma2(u64& c, u64 a, u64 b) {
    asm("fma.rn.f32x2 %0,%1,%2,%0;" : "+l"(c) : "l"(a), "l"(b));
}
__device__ __forceinline__ float2 upk(u64 v) {
    float2 f; asm("mov.b64 {%0,%1},%2;" : "=f"(f.x), "=f"(f.y) : "l"(v)); return f;
}

// ---------------- kernel 1: zero accumulators ----------------
__global__ void zero_acc_kernel() {
    int i = blockIdx.x * blockDim.x + threadIdx.x;
    if (i < 8 * Nn) ((float*)g_acc)[i] = 0.0f;
}

// ---------------- kernel 2: row L2-normalize (one warp per row) ----------------
__global__ void normalize_kernel(const float* __restrict__ z, int which) {
    float* out = which ? g_zsc : g_zmp;
    int row  = blockIdx.x * 8 + (threadIdx.x >> 5);
    int lane = threadIdx.x & 31;
    float2 v = ((const float2*)(z + (size_t)row * Dd))[lane];
    float s = v.x * v.x + v.y * v.y;
    #pragma unroll
    for (int o = 16; o; o >>= 1) s += __shfl_xor_sync(0xffffffffu, s, o);
    float inv = 1.0f / fmaxf(sqrtf(s), 1e-12f);
    float2 o2; o2.x = v.x * inv; o2.y = v.y * inv;
    ((float2*)(out + (size_t)row * Dd))[lane] = o2;
}

// ---------------- kernel 3: pack pos (binary fp32) into bitmask ----------------
__global__ void pack_pos_kernel(const float4* __restrict__ pos4) {
    unsigned idx4 = blockIdx.x * blockDim.x + threadIdx.x;   // one float4 per thread
    float4 v = pos4[idx4];
    unsigned nib = (v.x != 0.f ? 1u : 0u) | (v.y != 0.f ? 2u : 0u) |
                   (v.z != 0.f ? 4u : 0u) | (v.w != 0.f ? 8u : 0u);
    unsigned lane = threadIdx.x & 31;
    unsigned word = nib << (4 * (lane & 7));
    word |= __shfl_xor_sync(0xffffffffu, word, 1);
    word |= __shfl_xor_sync(0xffffffffu, word, 2);
    word |= __shfl_xor_sync(0xffffffffu, word, 4);
    if ((lane & 7) == 0) g_bits[idx4 >> 3] = word;
}

// ---------------- kernel 4: fused similarity + exp + masked reductions ----------------
// grid = (64, 64, 3); blockIdx.z: 0 = mp2sc (also does transposed/col terms), 1 = mp2mp, 2 = sc2sc
// 128x128 output tile per CTA, 256 threads, 8x8 per thread (split 4+4 rows/cols by 64).
#define SPAD 132   // smem row stride (keeps 16B alignment, decorrelates store banks)

__global__ __launch_bounds__(256) void sim_kernel() {
    const int mode = blockIdx.z;
    const float* Ap = (mode == 2) ? g_zsc : g_zmp;
    const float* Bp = (mode == 1) ? g_zmp : g_zsc;
    const int bi = blockIdx.y, bj = blockIdx.x;
    const int tid = threadIdx.x, tx = tid & 15, ty = tid >> 4;

    __shared__ float smem[2 * 32 * SPAD];
    float (*As)[SPAD] = (float(*)[SPAD])smem;
    float (*Bs)[SPAD] = (float(*)[SPAD])(smem + 32 * SPAD);

    // accumulators: row r in {ty*4+0..3, 64+ty*4+0..3}, col pair p covers cols
    // {tx*4, tx*4+1}, {tx*4+2, tx*4+3}, {64+tx*4,...}, {64+tx*4+2,...}
    u64 cc[8][4];
    #pragma unroll
    for (int r = 0; r < 8; r++)
        #pragma unroll
        for (int p = 0; p < 4; p++) cc[r][p] = 0ull;

    const int lm = tid >> 3, lc = tid & 7;
    const float* Ag = Ap + (size_t)bi * 128 * Dd;
    const float* Bg = Bp + (size_t)bj * 128 * Dd;

    for (int kc = 0; kc < 64; kc += 32) {
        #pragma unroll
        for (int it = 0; it < 4; ++it) {
            int m = lm + it * 32;
            float4 va = *(const float4*)(Ag + m * Dd + kc + lc * 4);
            As[lc * 4 + 0][m] = va.x; As[lc * 4 + 1][m] = va.y;
            As[lc * 4 + 2][m] = va.z; As[lc * 4 + 3][m] = va.w;
            float4 vb = *(const float4*)(Bg + m * Dd + kc + lc * 4);
            Bs[lc * 4 + 0][m] = vb.x; Bs[lc * 4 + 1][m] = vb.y;
            Bs[lc * 4 + 2][m] = vb.z; Bs[lc * 4 + 3][m] = vb.w;
        }
        __syncthreads();
        #pragma unroll
        for (int k = 0; k < 32; k++) {
            float4 a0 = *(const float4*)&As[k][ty * 4];
            float4 a1 = *(const float4*)&As[k][64 + ty * 4];
            float4 b0 = *(const float4*)&Bs[k][tx * 4];
            float4 b1 = *(const float4*)&Bs[k][64 + tx * 4];
            u64 bp[4] = { pk2(b0.x, b0.y), pk2(b0.z, b0.w),
                          pk2(b1.x, b1.y), pk2(b1.z, b1.w) };
            float ar[8] = { a0.x, a0.y, a0.z, a0.w, a1.x, a1.y, a1.z, a1.w };
            #pragma unroll
            for (int r = 0; r < 8; r++) {
                u64 ap = pk2s(ar[r]);
                #pragma unroll
                for (int p = 0; p < 4; p++) fma2(cc[r][p], ap, bp[p]);
            }
        }
        __syncthreads();
    }

    // ---------------- epilogue: exp + masked row/col partials ----------------
    float rsum[8], rpos[8], csum[8], cpos[8];
    #pragma unroll
    for (int r = 0; r < 8; r++) { rsum[r] = rpos[r] = csum[r] = cpos[r] = 0.f; }

    unsigned rw[8][2], cw[8][2];
    const int rbit = (tx * 4) & 31, cbit = (ty * 4) & 31;
    #pragma unroll
    for (int r = 0; r < 8; r++) {
        int gi = bi * 128 + (r >> 2) * 64 + ty * 4 + (r & 3);
        rw[r][0] = g_bits[gi * 256 + bj * 4 + 0 + (tx >> 3)];
        rw[r][1] = g_bits[gi * 256 + bj * 4 + 2 + (tx >> 3)];
    }
    if (mode == 0) {
        #pragma unroll
        for (int q = 0; q < 8; q++) {
            int gj = bj * 128 + (q >> 2) * 64 + tx * 4 + (q & 3);
            cw[q][0] = g_bits[gj * 256 + bi * 4 + 0 + (ty >> 3)];
            cw[q][1] = g_bits[gj * 256 + bi * 4 + 2 + (ty >> 3)];
        }
    }

    #pragma unroll
    for (int r = 0; r < 8; r++) {
        #pragma unroll
        for (int p = 0; p < 4; p++) {
            float2 s2 = upk(cc[r][p]);
            #pragma unroll
            for (int h = 0; h < 2; h++) {
                int q = p * 2 + h;
                float e = __expf(2.0f * (h ? s2.y : s2.x));   // exp(sim / 0.5)
                rsum[r] += e;
                if ((rw[r][p >> 1] >> (rbit + (q & 3))) & 1u) rpos[r] += e;
                if (mode == 0) {
                    csum[q] += e;
                    if ((cw[q][r >> 2] >> (cbit + (r & 3))) & 1u) cpos[q] += e;
                }
            }
        }
    }

    // ---------------- CTA reduction (reuse smem) + atomics ----------------
    float (*red)[SPAD] = (float(*)[SPAD])smem;
    const int accBase = (mode == 0) ? 0 : ((mode == 1) ? 4 : 6);

    for (int pass = 0; pass < 2; pass++) {
        __syncthreads();
        #pragma unroll
        for (int r = 0; r < 8; r++) {
            int rl = (r >> 2) * 64 + ty * 4 + (r & 3);
            red[tx][rl] = pass ? rpos[r] : rsum[r];
        }
        __syncthreads();
        if (tid < 128) {
            float s = 0.f;
            #pragma unroll
            for (int t = 0; t < 16; t++) s += red[t][tid];
            atomicAdd(&g_acc[accBase + pass][bi * 128 + tid], s);
        }
    }
    if (mode == 0) {
        for (int pass = 0; pass < 2; pass++) {
            __syncthreads();
            #pragma unroll
            for (int q = 0; q < 8; q++) {
                int cl = (q >> 2) * 64 + tx * 4 + (q & 3);
                red[ty][cl] = pass ? cpos[q] : csum[q];
            }
            __syncthreads();
            if (tid < 128) {
                float s = 0.f;
                #pragma unroll
                for (int t = 0; t < 16; t++) s += red[t][tid];
                atomicAdd(&g_acc[2 + pass][bj * 128 + tid], s);
            }
        }
    }
}

// ---------------- kernel 5: finalize loss ----------------
__global__ void finalize_kernel(float* out) {
    __shared__ double sred[256];
    double local = 0.0;
    for (int i = threadIdx.x; i < Nn; i += 256) {
        #pragma unroll
        for (int t = 0; t < 4; t++) {
            double A = (double)g_acc[2 * t][i];
            double B = (double)g_acc[2 * t + 1][i];
            local += log(B) - log(A + 1e-8);
        }
    }
    sred[threadIdx.x] = local;
    __syncthreads();
    for (int o = 128; o; o >>= 1) {
        if (threadIdx.x < o) sred[threadIdx.x] += sred[threadIdx.x + o];
        __syncthreads();
    }
    if (threadIdx.x == 0) out[0] = (float)(-sred[0] / (double)Nn);
}

// ---------------- launch ----------------
extern "C" void kernel_launch(void* const* d_in, const int* in_sizes, int n_in,
                              void* d_out, int out_size) {
    const float* z_mp = (const float*)d_in[0];
    const float* z_sc = (const float*)d_in[1];
    const float* pos  = (const float*)d_in[2];
    float* out = (float*)d_out;

    zero_acc_kernel<<<256, 256>>>();
    normalize_kernel<<<Nn / 8, 256>>>(z_mp, 0);
    normalize_kernel<<<Nn / 8, 256>>>(z_sc, 1);
    // N*N elements / 4 per thread / 256 threads per block = 65536 blocks
    pack_pos_kernel<<<(Nn / 4) * (Nn / 256), 256>>>((const float4*)pos);
    dim3 g(Nn / 128, Nn / 128, 3);
    sim_kernel<<<g, 256>>>();
    finalize_kernel<<<1, 256>>>(out);
}

// round 4
// speedup vs baseline: 2.0613x; 2.0613x over previous
#include <cuda_runtime.h>
#include <cuda_bf16.h>
#include <math.h>
#include <cstdint>

#define Nn 8192
#define Dd 64

// ---------------- device scratch ----------------
__device__ __nv_bfloat16 g_zmp_bf[Nn * Dd];
__device__ __nv_bfloat16 g_zsc_bf[Nn * Dd];
__device__ unsigned g_bits[(size_t)Nn * Nn / 32];   // pos bitmask, 8 MB
__device__ float    g_acc[8][Nn];                   // (A,B) for 4 terms

__device__ __forceinline__ unsigned smem_u32(const void* p) {
    unsigned a;
    asm("{ .reg .u64 t; cvta.to.shared.u64 t, %1; cvt.u32.u64 %0, t; }" : "=r"(a) : "l"(p));
    return a;
}

#define LDSM_X4(r0, r1, r2, r3, addr) \
    asm volatile("ldmatrix.sync.aligned.m8n8.x4.shared.b16 {%0,%1,%2,%3}, [%4];" \
                 : "=r"(r0), "=r"(r1), "=r"(r2), "=r"(r3) : "r"(addr))

#define MMA_BF16(c, a0, a1, a2, a3, b0, b1) \
    asm volatile("mma.sync.aligned.m16n8k16.row.col.f32.bf16.bf16.f32 " \
                 "{%0,%1,%2,%3}, {%4,%5,%6,%7}, {%8,%9}, {%0,%1,%2,%3};" \
                 : "+f"((c)[0]), "+f"((c)[1]), "+f"((c)[2]), "+f"((c)[3]) \
                 : "r"(a0), "r"(a1), "r"(a2), "r"(a3), "r"(b0), "r"(b1))

// ---------------- kernel 1: zero accumulators ----------------
__global__ void zero_acc_kernel() {
    int i = blockIdx.x * blockDim.x + threadIdx.x;
    if (i < 8 * Nn) ((float*)g_acc)[i] = 0.0f;
}

// ---------------- kernel 2: row L2-normalize -> bf16 ----------------
__global__ void normalize_kernel(const float* __restrict__ z, int which) {
    __nv_bfloat16* out = which ? g_zsc_bf : g_zmp_bf;
    int row  = blockIdx.x * 8 + (threadIdx.x >> 5);
    int lane = threadIdx.x & 31;
    float2 v = ((const float2*)(z + (size_t)row * Dd))[lane];
    float s = v.x * v.x + v.y * v.y;
    #pragma unroll
    for (int o = 16; o; o >>= 1) s += __shfl_xor_sync(0xffffffffu, s, o);
    float inv = 1.0f / fmaxf(sqrtf(s), 1e-12f);
    __nv_bfloat162 h = __floats2bfloat162_rn(v.x * inv, v.y * inv);
    ((__nv_bfloat162*)(out + (size_t)row * Dd))[lane] = h;
}

// ---------------- kernel 3: pack pos into bitmask ----------------
__global__ void pack_pos_kernel(const float4* __restrict__ pos4) {
    unsigned idx4 = blockIdx.x * blockDim.x + threadIdx.x;
    float4 v = pos4[idx4];
    unsigned nib = (v.x != 0.f ? 1u : 0u) | (v.y != 0.f ? 2u : 0u) |
                   (v.z != 0.f ? 4u : 0u) | (v.w != 0.f ? 8u : 0u);
    unsigned lane = threadIdx.x & 31;
    unsigned word = nib << (4 * (lane & 7));
    word |= __shfl_xor_sync(0xffffffffu, word, 1);
    word |= __shfl_xor_sync(0xffffffffu, word, 2);
    word |= __shfl_xor_sync(0xffffffffu, word, 4);
    if ((lane & 7) == 0) g_bits[idx4 >> 3] = word;
}

// ---------------- kernel 4: HMMA similarity + exp + masked row sums ----------------
// grid (64, 64, 4); mode: 0=(mp,sc) 1=(sc,mp) 2=(mp,mp) 3=(sc,sc). 128x128 tile/CTA.
// 8 warps; warp w computes rows w*16..w*16+15 x all 128 cols.
// SMEM tiles: 128 rows x 64 bf16 (128 B), chunk-swizzled: off = r*128 + ((c ^ (r&7)) << 4)
#define A_OFF    0
#define B_OFF    16384
#define BITS_OFF 32768      // 128 rows x uint4
#define SMEM_SZ  34816

__global__ __launch_bounds__(256) void sim_mma_kernel() {
    __shared__ __align__(128) unsigned char sm[SMEM_SZ];
    const unsigned smb = smem_u32(sm);

    const int mode = blockIdx.z;
    const __nv_bfloat16* Ap = (mode == 1 || mode == 3) ? g_zsc_bf : g_zmp_bf;
    const __nv_bfloat16* Bp = (mode == 0 || mode == 3) ? g_zsc_bf : g_zmp_bf;
    const int bi = blockIdx.y, bj = blockIdx.x;
    const int tid = threadIdx.x, lane = tid & 31, w = tid >> 5;

    // ---- stage tiles (swizzled) ----
    const __nv_bfloat16* Ag = Ap + (size_t)bi * 128 * Dd;
    const __nv_bfloat16* Bg = Bp + (size_t)bj * 128 * Dd;
    #pragma unroll
    for (int i = 0; i < 4; i++) {
        int seg = i * 256 + tid;                 // 1024 segs of 16 B per tile
        int row = seg >> 3, c = seg & 7;
        unsigned off = row * 128 + ((c ^ (row & 7)) << 4);
        *(uint4*)(sm + A_OFF + off) = ((const uint4*)(Ag + (size_t)row * Dd))[c];
        *(uint4*)(sm + B_OFF + off) = ((const uint4*)(Bg + (size_t)row * Dd))[c];
    }
    if (tid < 128)
        *(uint4*)(sm + BITS_OFF + tid * 16) =
            *(const uint4*)(g_bits + (size_t)(bi * 128 + tid) * 256 + bj * 4);
    __syncthreads();

    // ---- mainloop: 4 k-steps of m16n8k16 ----
    float acc[16][4];
    #pragma unroll
    for (int t = 0; t < 16; t++)
        #pragma unroll
        for (int j = 0; j < 4; j++) acc[t][j] = 0.f;

    const int rA = w * 16 + (lane & 15);          // A ldmatrix row
    const int cA_sel = lane >> 4;                 // A chunk select (k halves)
    const unsigned aBase = smb + A_OFF + rA * 128;
    const int nB = (lane & 7) + ((lane >> 4) & 1) * 8;  // B col within 16-col group
    const int cB_sel = (lane >> 3) & 1;

    #pragma unroll
    for (int ks = 0; ks < 4; ks++) {
        unsigned ca = 2 * ks + cA_sel;
        unsigned a0, a1, a2, a3;
        LDSM_X4(a0, a1, a2, a3, aBase + ((ca ^ (rA & 7)) << 4));
        #pragma unroll
        for (int t8 = 0; t8 < 8; t8++) {
            int col = t8 * 16 + nB;
            unsigned cb = 2 * ks + cB_sel;
            unsigned b0, b1, b2, b3;
            LDSM_X4(b0, b1, b2, b3, smb + B_OFF + col * 128 + ((cb ^ (col & 7)) << 4));
            MMA_BF16(acc[2 * t8 + 0], a0, a1, a2, a3, b0, b1);
            MMA_BF16(acc[2 * t8 + 1], a0, a1, a2, a3, b2, b3);
        }
    }

    // ---- epilogue: exp + mask, rows r_lo = w*16 + lane/4, r_hi = +8 ----
    const int qr = lane >> 2, qc = lane & 3;
    const int r_lo = w * 16 + qr, r_hi = r_lo + 8;
    uint4 wl4 = *(const uint4*)(sm + BITS_OFF + r_lo * 16);
    uint4 wh4 = *(const uint4*)(sm + BITS_OFF + r_hi * 16);
    unsigned wlo[4] = { wl4.x, wl4.y, wl4.z, wl4.w };
    unsigned whi[4] = { wh4.x, wh4.y, wh4.z, wh4.w };

    float s_lo = 0.f, p_lo = 0.f, s_hi = 0.f, p_hi = 0.f;
    #pragma unroll
    for (int t = 0; t < 16; t++) {
        const int wi = t >> 2, sb = (t & 3) * 8 + qc * 2;
        float e0 = __expf(acc[t][0] + acc[t][0]);
        float e1 = __expf(acc[t][1] + acc[t][1]);
        float e2 = __expf(acc[t][2] + acc[t][2]);
        float e3 = __expf(acc[t][3] + acc[t][3]);
        unsigned bl = wlo[wi] >> sb, bh = whi[wi] >> sb;
        s_lo += e0 + e1;
        s_hi += e2 + e3;
        p_lo += ((bl & 1u) ? e0 : 0.f) + ((bl & 2u) ? e1 : 0.f);
        p_hi += ((bh & 1u) ? e2 : 0.f) + ((bh & 2u) ? e3 : 0.f);
    }
    #pragma unroll
    for (int o = 1; o <= 2; o <<= 1) {
        s_lo += __shfl_xor_sync(0xffffffffu, s_lo, o);
        p_lo += __shfl_xor_sync(0xffffffffu, p_lo, o);
        s_hi += __shfl_xor_sync(0xffffffffu, s_hi, o);
        p_hi += __shfl_xor_sync(0xffffffffu, p_hi, o);
    }
    if (qc == 0) {
        atomicAdd(&g_acc[2 * mode + 0][bi * 128 + r_lo], s_lo);
        atomicAdd(&g_acc[2 * mode + 1][bi * 128 + r_lo], p_lo);
        atomicAdd(&g_acc[2 * mode + 0][bi * 128 + r_hi], s_hi);
        atomicAdd(&g_acc[2 * mode + 1][bi * 128 + r_hi], p_hi);
    }
}

// ---------------- kernel 5: finalize loss ----------------
__global__ void finalize_kernel(float* out) {
    __shared__ double sred[256];
    double local = 0.0;
    for (int i = threadIdx.x; i < Nn; i += 256) {
        #pragma unroll
        for (int t = 0; t < 4; t++) {
            double A = (double)g_acc[2 * t][i];
            double B = (double)g_acc[2 * t + 1][i];
            local += log(B) - log(A + 1e-8);
        }
    }
    sred[threadIdx.x] = local;
    __syncthreads();
    for (int o = 128; o; o >>= 1) {
        if (threadIdx.x < o) sred[threadIdx.x] += sred[threadIdx.x + o];
        __syncthreads();
    }
    if (threadIdx.x == 0) out[0] = (float)(-sred[0] / (double)Nn);
}

// ---------------- launch ----------------
extern "C" void kernel_launch(void* const* d_in, const int* in_sizes, int n_in,
                              void* d_out, int out_size) {
    const float* z_mp = (const float*)d_in[0];
    const float* z_sc = (const float*)d_in[1];
    const float* pos  = (const float*)d_in[2];
    float* out = (float*)d_out;

    zero_acc_kernel<<<256, 256>>>();
    normalize_kernel<<<Nn / 8, 256>>>(z_mp, 0);
    normalize_kernel<<<Nn / 8, 256>>>(z_sc, 1);
    pack_pos_kernel<<<(Nn / 4) * (Nn / 256), 256>>>((const float4*)pos);  // 65536 blocks
    dim3 g(Nn / 128, Nn / 128, 4);
    sim_mma_kernel<<<g, 256>>>();
    finalize_kernel<<<1, 256>>>(out);
}

// round 5
// speedup vs baseline: 2.4844x; 1.2053x over previous
#include <cuda_runtime.h>
#include <cuda_bf16.h>
#include <math.h>
#include <cstdint>

#define Nn 8192
#define Dd 64

// ---------------- device scratch ----------------
__device__ __nv_bfloat16 g_zmp_bf[Nn * Dd];
__device__ __nv_bfloat16 g_zsc_bf[Nn * Dd];
__device__ unsigned g_bits[(size_t)Nn * Nn / 32];   // pos bitmask, 8 MB
__device__ float    g_acc[8][Nn];                   // (A,B) for 4 terms

__device__ __forceinline__ unsigned smem_u32(const void* p) {
    unsigned a;
    asm("{ .reg .u64 t; cvta.to.shared.u64 t, %1; cvt.u32.u64 %0, t; }" : "=r"(a) : "l"(p));
    return a;
}

#define LDSM_X4(r0, r1, r2, r3, addr) \
    asm volatile("ldmatrix.sync.aligned.m8n8.x4.shared.b16 {%0,%1,%2,%3}, [%4];" \
                 : "=r"(r0), "=r"(r1), "=r"(r2), "=r"(r3) : "r"(addr))

#define MMA_BF16(c, a0, a1, a2, a3, b0, b1) \
    asm volatile("mma.sync.aligned.m16n8k16.row.col.f32.bf16.bf16.f32 " \
                 "{%0,%1,%2,%3}, {%4,%5,%6,%7}, {%8,%9}, {%0,%1,%2,%3};" \
                 : "+f"((c)[0]), "+f"((c)[1]), "+f"((c)[2]), "+f"((c)[3]) \
                 : "r"(a0), "r"(a1), "r"(a2), "r"(a3), "r"(b0), "r"(b1))

#define CP16(dst, src) \
    asm volatile("cp.async.cg.shared.global [%0], [%1], 16;" :: "r"(dst), "l"(src))
#define CP_COMMIT() asm volatile("cp.async.commit_group;" ::: "memory")
#define CP_WAIT0()  asm volatile("cp.async.wait_group 0;" ::: "memory")

// ---------------- kernel 1: zero accumulators ----------------
__global__ void zero_acc_kernel() {
    int i = blockIdx.x * blockDim.x + threadIdx.x;
    if (i < 8 * Nn) ((float*)g_acc)[i] = 0.0f;
}

// ---------------- kernel 2: row L2-normalize -> bf16 ----------------
__global__ void normalize_kernel(const float* __restrict__ z, int which) {
    __nv_bfloat16* out = which ? g_zsc_bf : g_zmp_bf;
    int row  = blockIdx.x * 8 + (threadIdx.x >> 5);
    int lane = threadIdx.x & 31;
    float2 v = ((const float2*)(z + (size_t)row * Dd))[lane];
    float s = v.x * v.x + v.y * v.y;
    #pragma unroll
    for (int o = 16; o; o >>= 1) s += __shfl_xor_sync(0xffffffffu, s, o);
    float inv = 1.0f / fmaxf(sqrtf(s), 1e-12f);
    __nv_bfloat162 h = __floats2bfloat162_rn(v.x * inv, v.y * inv);
    ((__nv_bfloat162*)(out + (size_t)row * Dd))[lane] = h;
}

// ---------------- kernel 3: pack pos into bitmask (2-way MLP) ----------------
#define PK_HALF (Nn * (size_t)Nn / 8)      // float4s per half
__global__ void pack_pos_kernel(const float4* __restrict__ pos4) {
    unsigned base = blockIdx.x * blockDim.x + threadIdx.x;
    unsigned lane = threadIdx.x & 31;
    #pragma unroll
    for (int h = 0; h < 2; h++) {
        unsigned idx4 = base + (unsigned)(h * PK_HALF);
        float4 v = pos4[idx4];
        unsigned nib = (v.x != 0.f ? 1u : 0u) | (v.y != 0.f ? 2u : 0u) |
                       (v.z != 0.f ? 4u : 0u) | (v.w != 0.f ? 8u : 0u);
        unsigned word = nib << (4 * (lane & 7));
        word |= __shfl_xor_sync(0xffffffffu, word, 1);
        word |= __shfl_xor_sync(0xffffffffu, word, 2);
        word |= __shfl_xor_sync(0xffffffffu, word, 4);
        if ((lane & 7) == 0) g_bits[idx4 >> 3] = word;
    }
}

// ---------------- kernel 4: HMMA similarity, streaming 32-col blocks ----------------
// grid (64, 64, 4); mode: 0=(mp,sc) 1=(sc,mp) 2=(mp,mp) 3=(sc,sc). 128x128 tile/CTA.
// 8 warps; warp w owns rows w*16..+15. A frags cached across k; N streamed in 4 blocks
// of 32 cols with immediate exp/mask epilogue (only 16 live accums).
#define A_OFF    0
#define B_OFF    16384
#define BITS_OFF 32768      // 128 rows x uint4
#define SMEM_SZ  34816

__global__ __launch_bounds__(256, 3) void sim_mma_kernel() {
    __shared__ __align__(128) unsigned char sm[SMEM_SZ];
    const unsigned smb = smem_u32(sm);

    const int mode = blockIdx.z;
    const __nv_bfloat16* Ap = (mode == 1 || mode == 3) ? g_zsc_bf : g_zmp_bf;
    const __nv_bfloat16* Bp = (mode == 0 || mode == 3) ? g_zsc_bf : g_zmp_bf;
    const int bi = blockIdx.y, bj = blockIdx.x;
    const int tid = threadIdx.x, lane = tid & 31, w = tid >> 5;

    // ---- stage tiles (swizzled) via cp.async ----
    const char* Ag = (const char*)(Ap + (size_t)bi * 128 * Dd);
    const char* Bg = (const char*)(Bp + (size_t)bj * 128 * Dd);
    #pragma unroll
    for (int i = 0; i < 4; i++) {
        int seg = i * 256 + tid;                 // 1024 segs of 16 B per tile
        int row = seg >> 3, c = seg & 7;
        unsigned off = row * 128 + ((c ^ (row & 7)) << 4);
        CP16(smb + A_OFF + off, Ag + row * 128 + c * 16);
        CP16(smb + B_OFF + off, Bg + row * 128 + c * 16);
    }
    if (tid < 128)
        CP16(smb + BITS_OFF + tid * 16,
             (const char*)(g_bits + (size_t)(bi * 128 + tid) * 256 + bj * 4));
    CP_COMMIT();
    CP_WAIT0();
    __syncthreads();

    // ---- A fragments for all 4 k-steps (held in regs) ----
    const int rA = w * 16 + (lane & 15);
    const int cA_sel = lane >> 4;
    const unsigned aBase = smb + A_OFF + rA * 128;
    unsigned a[4][4];
    #pragma unroll
    for (int ks = 0; ks < 4; ks++) {
        unsigned ca = 2 * ks + cA_sel;
        LDSM_X4(a[ks][0], a[ks][1], a[ks][2], a[ks][3], aBase + ((ca ^ (rA & 7)) << 4));
    }

    const int nB = (lane & 7) + ((lane >> 4) & 1) * 8;
    const int cB_sel = (lane >> 3) & 1;
    const int qr = lane >> 2, qc = lane & 3;
    const int r_lo = w * 16 + qr, r_hi = r_lo + 8;

    uint4 wl4 = *(const uint4*)(sm + BITS_OFF + r_lo * 16);
    uint4 wh4 = *(const uint4*)(sm + BITS_OFF + r_hi * 16);
    unsigned wlo[4] = { wl4.x, wl4.y, wl4.z, wl4.w };
    unsigned whi[4] = { wh4.x, wh4.y, wh4.z, wh4.w };

    float s_lo = 0.f, p_lo = 0.f, s_hi = 0.f, p_hi = 0.f;

    #pragma unroll
    for (int nb = 0; nb < 4; nb++) {
        float acc[4][4];
        #pragma unroll
        for (int u = 0; u < 4; u++)
            #pragma unroll
            for (int j = 0; j < 4; j++) acc[u][j] = 0.f;

        #pragma unroll
        for (int ks = 0; ks < 4; ks++) {
            unsigned cb = 2 * ks + cB_sel;
            #pragma unroll
            for (int g = 0; g < 2; g++) {
                int col = nb * 32 + g * 16 + nB;
                unsigned b0, b1, b2, b3;
                LDSM_X4(b0, b1, b2, b3, smb + B_OFF + col * 128 + ((cb ^ (col & 7)) << 4));
                MMA_BF16(acc[2 * g + 0], a[ks][0], a[ks][1], a[ks][2], a[ks][3], b0, b1);
                MMA_BF16(acc[2 * g + 1], a[ks][0], a[ks][1], a[ks][2], a[ks][3], b2, b3);
            }
        }

        // epilogue for this 32-col block (acc[u] covers cols nb*32 + u*8 + qc*2 + {0,1})
        const unsigned bl = wlo[nb], bh = whi[nb];
        #pragma unroll
        for (int u = 0; u < 4; u++) {
            const int sb = u * 8 + qc * 2;
            float e0 = __expf(acc[u][0] + acc[u][0]);
            float e1 = __expf(acc[u][1] + acc[u][1]);
            float e2 = __expf(acc[u][2] + acc[u][2]);
            float e3 = __expf(acc[u][3] + acc[u][3]);
            unsigned l = bl >> sb, h = bh >> sb;
            s_lo += e0 + e1;
            s_hi += e2 + e3;
            p_lo += ((l & 1u) ? e0 : 0.f) + ((l & 2u) ? e1 : 0.f);
            p_hi += ((h & 1u) ? e2 : 0.f) + ((h & 2u) ? e3 : 0.f);
        }
    }

    #pragma unroll
    for (int o = 1; o <= 2; o <<= 1) {
        s_lo += __shfl_xor_sync(0xffffffffu, s_lo, o);
        p_lo += __shfl_xor_sync(0xffffffffu, p_lo, o);
        s_hi += __shfl_xor_sync(0xffffffffu, s_hi, o);
        p_hi += __shfl_xor_sync(0xffffffffu, p_hi, o);
    }
    if (qc == 0) {
        atomicAdd(&g_acc[2 * mode + 0][bi * 128 + r_lo], s_lo);
        atomicAdd(&g_acc[2 * mode + 1][bi * 128 + r_lo], p_lo);
        atomicAdd(&g_acc[2 * mode + 0][bi * 128 + r_hi], s_hi);
        atomicAdd(&g_acc[2 * mode + 1][bi * 128 + r_hi], p_hi);
    }
}

// ---------------- kernel 5: finalize loss ----------------
__global__ void finalize_kernel(float* out) {
    __shared__ double sred[256];
    double local = 0.0;
    for (int i = threadIdx.x; i < Nn; i += 256) {
        #pragma unroll
        for (int t = 0; t < 4; t++) {
            double A = (double)g_acc[2 * t][i];
            double B = (double)g_acc[2 * t + 1][i];
            local += log(B) - log(A + 1e-8);
        }
    }
    sred[threadIdx.x] = local;
    __syncthreads();
    for (int o = 128; o; o >>= 1) {
        if (threadIdx.x < o) sred[threadIdx.x] += sred[threadIdx.x + o];
        __syncthreads();
    }
    if (threadIdx.x == 0) out[0] = (float)(-sred[0] / (double)Nn);
}

// ---------------- launch ----------------
extern "C" void kernel_launch(void* const* d_in, const int* in_sizes, int n_in,
                              void* d_out, int out_size) {
    const float* z_mp = (const float*)d_in[0];
    const float* z_sc = (const float*)d_in[1];
    const float* pos  = (const float*)d_in[2];
    float* out = (float*)d_out;

    zero_acc_kernel<<<256, 256>>>();
    normalize_kernel<<<Nn / 8, 256>>>(z_mp, 0);
    normalize_kernel<<<Nn / 8, 256>>>(z_sc, 1);
    pack_pos_kernel<<<32768, 256>>>((const float4*)pos);   // 2 float4s per thread
    dim3 g(Nn / 128, Nn / 128, 4);
    sim_mma_kernel<<<g, 256>>>();
    finalize_kernel<<<1, 256>>>(out);
}